// round 1
// baseline (speedup 1.0000x reference)
#include <cuda_runtime.h>
#include <cstdint>

// Problem: B=16384, N=64, D=64, O=64
//  Wh = h @ W ; robot = Wh[:,0]; others = Wh[:,1:]
//  scores = others@a2 + (robot@a1)[:,None]  -> softmax over axis 1
//    NOTE: robot@a1 is constant along softmax axis -> cancels. a1 unused.
//  out = elu(concat(robot, attn*others))
// Fused: v2 = W@a2 (prep kernel). Per batch:
//  dots[n] = h[n]·v2 (n=1..63) -> softmax -> factor (factor[0]=1)
//  scale h rows by factor, round tf32, GEMM (attn*h)@W via mma.sync tf32, elu.

#define GB 8      // batches per CTA
#define HS 68     // h smem row stride (floats) — conflict-free A-frag loads
#define WS 72     // W smem row stride (floats) — conflict-free B-frag loads

__device__ float g_v2[64];

__global__ void prep_v2_kernel(const float* __restrict__ W,
                               const float* __restrict__ a) {
    int d = threadIdx.x;
    if (d < 64) {
        const float* a2 = a + 64;
        float s = 0.f;
#pragma unroll
        for (int o = 0; o < 64; ++o) s = fmaf(W[d * 64 + o], a2[o], s);
        g_v2[d] = s;
    }
}

__device__ __forceinline__ unsigned f2tf32(float x) {
    unsigned r;
    asm("cvt.rna.tf32.f32 %0, %1;" : "=r"(r) : "f"(x));
    return r;
}

__device__ __forceinline__ float elu1(float x) {
    return x > 0.f ? x : expm1f(x);
}

__global__ __launch_bounds__(128)
void gat_fused_kernel(const float* __restrict__ h,
                      const float* __restrict__ W,
                      float* __restrict__ out) {
    __shared__ float sW[64 * WS];
    __shared__ float sh[64 * HS];
    __shared__ float sdots[64];
    __shared__ float sfac[64];
    __shared__ float sv2[64];

    const int tid  = threadIdx.x;
    const int lane = tid & 31;
    const int warp = tid >> 5;
    const int gid  = lane >> 2;   // groupID
    const int tig  = lane & 3;    // thread in group

    // Fill W smem (pre-rounded to tf32) and v2 once per CTA.
    for (int i = tid; i < 4096; i += 128) {
        int d = i >> 6, o = i & 63;
        sW[d * WS + o] = __uint_as_float(f2tf32(W[i]));
    }
    if (tid < 64) sv2[tid] = g_v2[tid];
    __syncthreads();

    for (int g = 0; g < GB; ++g) {
        const int b = blockIdx.x * GB + g;
        const float* hb = h + (size_t)b * 4096;

        // ---- load h[b] into smem (fp32, coalesced float4) ----
        for (int i = tid; i < 1024; i += 128) {
            float4 v = reinterpret_cast<const float4*>(hb)[i];
            float* p = &sh[(i >> 4) * HS + ((i & 15) << 2)];
            p[0] = v.x; p[1] = v.y; p[2] = v.z; p[3] = v.w;
        }
        __syncthreads();

        // ---- dots[n] = h[n]·v2 for n=1..63 (fp32 exact path) ----
        if (tid >= 1 && tid < 64) {
            float s = 0.f;
#pragma unroll
            for (int d = 0; d < 64; ++d)
                s = fmaf(sh[tid * HS + d], sv2[d], s);
            sdots[tid] = s;
        }
        __syncthreads();

        // ---- softmax over 63 scores (warp 0) -> sfac ----
        if (warp == 0) {
            float x0 = (lane >= 1) ? sdots[lane] : -1e30f;
            float x1 = sdots[lane + 32];           // rows 32..63, all valid
            float m = fmaxf(x0, x1);
#pragma unroll
            for (int off = 16; off; off >>= 1)
                m = fmaxf(m, __shfl_xor_sync(0xffffffffu, m, off));
            float e0 = (lane >= 1) ? expf(x0 - m) : 0.f;
            float e1 = expf(x1 - m);
            float s = e0 + e1;
#pragma unroll
            for (int off = 16; off; off >>= 1)
                s += __shfl_xor_sync(0xffffffffu, s, off);
            float inv = 1.f / s;
            if (lane >= 1) sfac[lane] = e0 * inv;
            sfac[lane + 32] = e1 * inv;
            if (lane == 0) sfac[0] = 1.f;          // robot row unscaled
        }
        __syncthreads();

        // ---- scale rows by factor + round to tf32, in place ----
        for (int i = tid; i < 1024; i += 128) {
            int row = i >> 4;
            float f = sfac[row];
            float* p = &sh[row * HS + ((i & 15) << 2)];
#pragma unroll
            for (int k = 0; k < 4; ++k)
                p[k] = __uint_as_float(f2tf32(p[k] * f));
        }
        __syncthreads();

        // ---- GEMM: warp w computes rows [16w, 16w+16) x all 64 cols ----
        float acc[8][4];
#pragma unroll
        for (int nn = 0; nn < 8; ++nn)
#pragma unroll
            for (int k = 0; k < 4; ++k) acc[nn][k] = 0.f;

        const int r0 = warp * 16 + gid;
#pragma unroll
        for (int kk = 0; kk < 8; ++kk) {
            const int c = kk * 8 + tig;
            unsigned a0 = __float_as_uint(sh[r0 * HS + c]);
            unsigned a1 = __float_as_uint(sh[(r0 + 8) * HS + c]);
            unsigned a2 = __float_as_uint(sh[r0 * HS + c + 4]);
            unsigned a3 = __float_as_uint(sh[(r0 + 8) * HS + c + 4]);
#pragma unroll
            for (int nn = 0; nn < 8; ++nn) {
                unsigned b0 = __float_as_uint(sW[(kk * 8 + tig) * WS + nn * 8 + gid]);
                unsigned b1 = __float_as_uint(sW[(kk * 8 + tig + 4) * WS + nn * 8 + gid]);
                asm volatile(
                    "mma.sync.aligned.m16n8k8.row.col.f32.tf32.tf32.f32 "
                    "{%0,%1,%2,%3}, {%4,%5,%6,%7}, {%8,%9}, {%0,%1,%2,%3};"
                    : "+f"(acc[nn][0]), "+f"(acc[nn][1]),
                      "+f"(acc[nn][2]), "+f"(acc[nn][3])
                    : "r"(a0), "r"(a1), "r"(a2), "r"(a3), "r"(b0), "r"(b1));
            }
        }

        // ---- epilogue: elu + store ----
        float* ob = out + (size_t)b * 4096;
        const int rA = warp * 16 + gid;
        const int rB = rA + 8;
#pragma unroll
        for (int nn = 0; nn < 8; ++nn) {
            int col = nn * 8 + tig * 2;
            float2 v0 = make_float2(elu1(acc[nn][0]), elu1(acc[nn][1]));
            float2 v1 = make_float2(elu1(acc[nn][2]), elu1(acc[nn][3]));
            *reinterpret_cast<float2*>(ob + rA * 64 + col) = v0;
            *reinterpret_cast<float2*>(ob + rB * 64 + col) = v1;
        }
        __syncthreads();   // protect sh before next batch's load
    }
}

extern "C" void kernel_launch(void* const* d_in, const int* in_sizes, int n_in,
                              void* d_out, int out_size) {
    const float* h = (const float*)d_in[0];   // (16384, 64, 64) f32
    const float* W = (const float*)d_in[1];   // (64, 64) f32
    const float* a = (const float*)d_in[2];   // (128, 1) f32
    float* out = (float*)d_out;               // (16384, 64, 64) f32

    prep_v2_kernel<<<1, 64>>>(W, a);
    gat_fused_kernel<<<16384 / GB, 128>>>(h, W, out);
}

// round 2
// speedup vs baseline: 1.2355x; 1.2355x over previous
#include <cuda_runtime.h>
#include <cstdint>

// B=16384, N=64, D=64, O=64
// softmax(others@a2 + (robot@a1)) == softmax(others@a2)  (robot term constant per row)
// out = elu( (diag(1,attn) * h) @ W )
// v2 = W@a2 precomputed. Per batch: dots -> softmax -> fold factor into A-frag
// (registers) -> tf32 mma with pre-packed W fragments -> elu -> store.
// cp.async double-buffering of h.

#define GB 8      // batches per CTA
#define HS 68     // h smem row stride (floats): 68 % 32 == 4 -> A-frag conflict-free

__device__ float g_v2[64];

__global__ void prep_v2_kernel(const float* __restrict__ W,
                               const float* __restrict__ a) {
    int d = threadIdx.x;
    if (d < 64) {
        const float* a2 = a + 64;
        float s = 0.f;
#pragma unroll
        for (int o = 0; o < 64; ++o) s = fmaf(W[d * 64 + o], a2[o], s);
        g_v2[d] = s;
    }
}

__device__ __forceinline__ unsigned f2tf32(float x) {
    unsigned r;
    asm("cvt.rna.tf32.f32 %0, %1;" : "=r"(r) : "f"(x));
    return r;
}

__device__ __forceinline__ float elu1(float x) {
    return x > 0.f ? x : expm1f(x);
}

__device__ __forceinline__ void cp_async16(uint32_t saddr, const void* gptr) {
    asm volatile("cp.async.cg.shared.global [%0], [%1], 16;\n"
                 :: "r"(saddr), "l"(gptr));
}

__global__ __launch_bounds__(128)
void gat_fused_kernel(const float* __restrict__ h,
                      const float* __restrict__ W,
                      float* __restrict__ out) {
    __shared__ float  sh[2][64 * HS];          // double-buffered h (fp32)
    __shared__ float2 sWf[64 * 32];            // W B-fragments [kk*8+nn][lane]
    __shared__ float  sdots[64];
    __shared__ float  sfac[64];
    __shared__ float  sv2[64];

    const int tid  = threadIdx.x;
    const int lane = tid & 31;
    const int warp = tid >> 5;
    const int gid  = lane >> 2;   // groupID  (0..7)
    const int tig  = lane & 3;    // thread-in-group (0..3)

    // ---- pack W into per-lane tf32 B-fragment layout (once per CTA) ----
    // b0 = W[k=kk*8+tig][n=nn*8+gid], b1 = W[k=kk*8+tig+4][n=nn*8+gid]
    {
#pragma unroll
        for (int j = 0; j < 2; ++j) {
            int kk = warp * 2 + j;
            int krow = kk * 8 + tig;
#pragma unroll
            for (int nn = 0; nn < 8; ++nn) {
                float b0 = W[krow * 64 + nn * 8 + gid];
                float b1 = W[(krow + 4) * 64 + nn * 8 + gid];
                sWf[(kk * 8 + nn) * 32 + lane] =
                    make_float2(__uint_as_float(f2tf32(b0)),
                                __uint_as_float(f2tf32(b1)));
            }
        }
    }
    if (tid < 64) sv2[tid] = g_v2[tid];

    const size_t base = (size_t)blockIdx.x * GB * 4096;

    // ---- prefetch batch 0 ----
    {
        const float* hb = h + base;
        uint32_t sb = (uint32_t)__cvta_generic_to_shared(&sh[0][0]);
#pragma unroll
        for (int c = tid; c < 1024; c += 128) {
            int row = c >> 4, q = c & 15;
            cp_async16(sb + (row * HS + q * 4) * 4, hb + c * 4);
        }
        asm volatile("cp.async.commit_group;\n");
    }

    for (int g = 0; g < GB; ++g) {
        const int buf = g & 1;

        asm volatile("cp.async.wait_group 0;\n");
        __syncthreads();   // h[g] visible to all; all warps done with iter g-1

        // ---- prefetch batch g+1 into other buffer ----
        if (g + 1 < GB) {
            const float* hb = h + base + (size_t)(g + 1) * 4096;
            uint32_t sb = (uint32_t)__cvta_generic_to_shared(&sh[buf ^ 1][0]);
#pragma unroll
            for (int c = tid; c < 1024; c += 128) {
                int row = c >> 4, q = c & 15;
                cp_async16(sb + (row * HS + q * 4) * 4, hb + c * 4);
            }
            asm volatile("cp.async.commit_group;\n");
        }

        // ---- dots[n] = h[n]·v2 : 2 threads per row, float4 loads ----
        {
            int row = tid >> 1;
            int off = (tid & 1) << 5;          // 0 or 32
            const float4* hp = reinterpret_cast<const float4*>(&sh[buf][row * HS + off]);
            const float4* vp = reinterpret_cast<const float4*>(&sv2[off]);
            float s = 0.f;
#pragma unroll
            for (int k = 0; k < 8; ++k) {
                float4 hv = hp[k];
                float4 vv = vp[k];
                s = fmaf(hv.x, vv.x, s);
                s = fmaf(hv.y, vv.y, s);
                s = fmaf(hv.z, vv.z, s);
                s = fmaf(hv.w, vv.w, s);
            }
            s += __shfl_xor_sync(0xffffffffu, s, 1);
            if ((tid & 1) == 0) sdots[row] = s;
        }
        __syncthreads();

        // ---- softmax over scores 1..63 (warp 0) -> sfac ----
        if (warp == 0) {
            float x0 = (lane >= 1) ? sdots[lane] : -1e30f;
            float x1 = sdots[lane + 32];
            float m = fmaxf(x0, x1);
#pragma unroll
            for (int off = 16; off; off >>= 1)
                m = fmaxf(m, __shfl_xor_sync(0xffffffffu, m, off));
            float e0 = (lane >= 1) ? expf(x0 - m) : 0.f;
            float e1 = expf(x1 - m);
            float s = e0 + e1;
#pragma unroll
            for (int off = 16; off; off >>= 1)
                s += __shfl_xor_sync(0xffffffffu, s, off);
            float inv = 1.f / s;
            if (lane >= 1) sfac[lane] = e0 * inv;
            sfac[lane + 32] = e1 * inv;
            if (lane == 0) sfac[0] = 1.f;   // robot row unscaled
        }
        __syncthreads();

        // ---- GEMM: warp w -> rows [16w,16w+16), factor folded in registers ----
        float acc[8][4];
#pragma unroll
        for (int nn = 0; nn < 8; ++nn)
#pragma unroll
            for (int k = 0; k < 4; ++k) acc[nn][k] = 0.f;

        const int r0 = warp * 16 + gid;
        const float fA = sfac[r0];
        const float fB = sfac[r0 + 8];
        const float* shb = &sh[buf][0];

#pragma unroll
        for (int kk = 0; kk < 8; ++kk) {
            const int c = kk * 8 + tig;
            unsigned a0 = f2tf32(shb[r0 * HS + c] * fA);
            unsigned a1 = f2tf32(shb[(r0 + 8) * HS + c] * fB);
            unsigned a2 = f2tf32(shb[r0 * HS + c + 4] * fA);
            unsigned a3 = f2tf32(shb[(r0 + 8) * HS + c + 4] * fB);
            const float2* wf = &sWf[(kk * 8) * 32 + lane];
#pragma unroll
            for (int nn = 0; nn < 8; ++nn) {
                float2 bb = wf[nn * 32];
                asm volatile(
                    "mma.sync.aligned.m16n8k8.row.col.f32.tf32.tf32.f32 "
                    "{%0,%1,%2,%3}, {%4,%5,%6,%7}, {%8,%9}, {%0,%1,%2,%3};"
                    : "+f"(acc[nn][0]), "+f"(acc[nn][1]),
                      "+f"(acc[nn][2]), "+f"(acc[nn][3])
                    : "r"(a0), "r"(a1), "r"(a2), "r"(a3),
                      "r"(__float_as_uint(bb.x)), "r"(__float_as_uint(bb.y)));
            }
        }

        // ---- epilogue: elu + store ----
        float* ob = out + base + (size_t)g * 4096;
        const int rB = r0 + 8;
#pragma unroll
        for (int nn = 0; nn < 8; ++nn) {
            int col = nn * 8 + tig * 2;
            float2 v0 = make_float2(elu1(acc[nn][0]), elu1(acc[nn][1]));
            float2 v1 = make_float2(elu1(acc[nn][2]), elu1(acc[nn][3]));
            *reinterpret_cast<float2*>(ob + r0 * 64 + col) = v0;
            *reinterpret_cast<float2*>(ob + rB * 64 + col) = v1;
        }
    }
}

extern "C" void kernel_launch(void* const* d_in, const int* in_sizes, int n_in,
                              void* d_out, int out_size) {
    const float* h = (const float*)d_in[0];   // (16384, 64, 64) f32
    const float* W = (const float*)d_in[1];   // (64, 64) f32
    const float* a = (const float*)d_in[2];   // (128, 1) f32
    float* out = (float*)d_out;               // (16384, 64, 64) f32

    prep_v2_kernel<<<1, 64>>>(W, a);
    gat_fused_kernel<<<16384 / GB, 128>>>(h, W, out);
}